// round 2
// baseline (speedup 1.0000x reference)
#include <cuda_runtime.h>
#include <math.h>

#define B_    4
#define L_    2048
#define DM    2048
#define DI    4096
#define DST   64
#define HN    64
#define HP    64
#define CONVD 4224
#define DIP   8448
#define BL    (B_*L_)          // 8192
#define NCLS  4

// ---------------- scratch (static device globals; no allocation) ----------------
__device__ float g_zx[BL * DIP];        // in_proj output  (8192 x 8448)  277 MB
__device__ float g_xh[BL * DI];         // conv+silu x part (8192 x 4096) 134 MB
__device__ float g_Bm[BL * DST];        // conv+silu B      (8192 x 64)
__device__ float g_Cm[BL * DST];        // conv+silu C
__device__ float g_dt[BL * HN];         // softplus dt
__device__ float g_dA[BL * HN];         // exp(-exp(A_log)*dt)
__device__ float g_y [BL * DI];         // scan output (gated), then normed in place
__device__ float g_oh[BL * DM];         // out_proj output

// ---------------- generic fp32 SIMT GEMM:  C[M,N] = A[M,K] * W[N,K]^T ----------------
// 128x128 tile, Ktile=16, 256 threads, 8x8 microtile. M,N multiples of 128; K multiple of 16.
__global__ __launch_bounds__(256, 2)
void gemm_nt_128(const float* __restrict__ A, const float* __restrict__ W,
                 float* __restrict__ C, int M, int N, int K)
{
    __shared__ __align__(16) float As[16][132];
    __shared__ __align__(16) float Ws[16][132];
    const int tid = threadIdx.x;
    const int bm  = blockIdx.y << 7;
    const int bn  = blockIdx.x << 7;
    const int tm  = (tid >> 4) << 3;
    const int tn  = (tid & 15) << 3;

    float acc[8][8];
    #pragma unroll
    for (int i = 0; i < 8; i++)
        #pragma unroll
        for (int j = 0; j < 8; j++) acc[i][j] = 0.f;

    for (int k0 = 0; k0 < K; k0 += 16) {
        #pragma unroll
        for (int i = 0; i < 2; i++) {
            int idx = tid + (i << 8);            // 0..511
            int row = idx >> 2;                  // 0..127
            int kv  = (idx & 3) << 2;            // 0,4,8,12
            float4 av = *(const float4*)(A + (size_t)(bm + row) * K + k0 + kv);
            As[kv + 0][row] = av.x; As[kv + 1][row] = av.y;
            As[kv + 2][row] = av.z; As[kv + 3][row] = av.w;
            float4 wv = *(const float4*)(W + (size_t)(bn + row) * K + k0 + kv);
            Ws[kv + 0][row] = wv.x; Ws[kv + 1][row] = wv.y;
            Ws[kv + 2][row] = wv.z; Ws[kv + 3][row] = wv.w;
        }
        __syncthreads();
        #pragma unroll
        for (int k = 0; k < 16; k++) {
            float a[8], b[8];
            float4 a0 = *(const float4*)&As[k][tm];
            float4 a1 = *(const float4*)&As[k][tm + 4];
            float4 b0 = *(const float4*)&Ws[k][tn];
            float4 b1 = *(const float4*)&Ws[k][tn + 4];
            a[0]=a0.x; a[1]=a0.y; a[2]=a0.z; a[3]=a0.w;
            a[4]=a1.x; a[5]=a1.y; a[6]=a1.z; a[7]=a1.w;
            b[0]=b0.x; b[1]=b0.y; b[2]=b0.z; b[3]=b0.w;
            b[4]=b1.x; b[5]=b1.y; b[6]=b1.z; b[7]=b1.w;
            #pragma unroll
            for (int i = 0; i < 8; i++)
                #pragma unroll
                for (int j = 0; j < 8; j++)
                    acc[i][j] = fmaf(a[i], b[j], acc[i][j]);
        }
        __syncthreads();
    }
    #pragma unroll
    for (int i = 0; i < 8; i++) {
        float* crow = C + (size_t)(bm + tm + i) * N + bn + tn;
        float4 o0 = make_float4(acc[i][0], acc[i][1], acc[i][2], acc[i][3]);
        float4 o1 = make_float4(acc[i][4], acc[i][5], acc[i][6], acc[i][7]);
        *(float4*)(crow)     = o0;
        *(float4*)(crow + 4) = o1;
    }
}

// ---------------- conv1d(depthwise, width 4) + SiLU + dt/dA prep ----------------
__global__ void conv_prep_kernel(const float* __restrict__ conv_w,
                                 const float* __restrict__ conv_b,
                                 const float* __restrict__ dt_bias,
                                 const float* __restrict__ A_log)
{
    const int bt = blockIdx.x;        // 0..8191
    const int b  = bt / L_;
    const int t  = bt % L_;

    for (int c = threadIdx.x; c < CONVD; c += blockDim.x) {
        float4 wv = *(const float4*)(conv_w + c * 4);
        float s = conv_b[c];
        const float wk[4] = {wv.x, wv.y, wv.z, wv.w};
        #pragma unroll
        for (int k = 0; k < 4; k++) {
            int tt = t - 3 + k;
            float xv = (tt >= 0) ? g_zx[(size_t)(b * L_ + tt) * DIP + DI + c] : 0.f;
            s = fmaf(xv, wk[k], s);
        }
        float sil = s / (1.f + expf(-s));
        if (c < DI)            g_xh[(size_t)bt * DI + c]      = sil;
        else if (c < DI + DST) g_Bm[bt * DST + (c - DI)]       = sil;
        else                   g_Cm[bt * DST + (c - DI - DST)] = sil;
    }
    if (threadIdx.x < HN) {
        int h = threadIdx.x;
        float dtr = g_zx[(size_t)bt * DIP + DI + CONVD + h] + dt_bias[h];
        float dts = (dtr > 20.f) ? dtr : log1pf(expf(dtr));
        g_dt[bt * HN + h] = dts;
        g_dA[bt * HN + h] = expf(-expf(A_log[h]) * dts);
    }
}

// ---------------- sequential selective scan + D*x + silu(z) gating ----------------
// block = (b, h), 64 threads = p; each thread keeps D_STATE=64 states in registers.
__global__ __launch_bounds__(64)
void scan_kernel(const float* __restrict__ Dp)
{
    const int b = blockIdx.x >> 6;
    const int h = blockIdx.x & 63;
    const int p = threadIdx.x;
    const float Dh = __ldg(Dp + h);

    float hs[DST];
    #pragma unroll
    for (int n = 0; n < DST; n++) hs[n] = 0.f;

    for (int t = 0; t < L_; t++) {
        const int bt = b * L_ + t;
        const float dA = __ldg(&g_dA[bt * HN + h]);
        const float dt = __ldg(&g_dt[bt * HN + h]);
        const float xv = g_xh[(size_t)bt * DI + h * HP + p];
        const float u  = dt * xv;
        const float4* Bv = (const float4*)(g_Bm + bt * DST);
        const float4* Cv = (const float4*)(g_Cm + bt * DST);
        float acc = 0.f;
        #pragma unroll
        for (int j = 0; j < 16; j++) {
            float4 Bq = __ldg(&Bv[j]);
            float4 Cq = __ldg(&Cv[j]);
            hs[4*j+0] = fmaf(hs[4*j+0], dA, u * Bq.x); acc = fmaf(hs[4*j+0], Cq.x, acc);
            hs[4*j+1] = fmaf(hs[4*j+1], dA, u * Bq.y); acc = fmaf(hs[4*j+1], Cq.y, acc);
            hs[4*j+2] = fmaf(hs[4*j+2], dA, u * Bq.z); acc = fmaf(hs[4*j+2], Cq.z, acc);
            hs[4*j+3] = fmaf(hs[4*j+3], dA, u * Bq.w); acc = fmaf(hs[4*j+3], Cq.w, acc);
        }
        const float z = g_zx[(size_t)bt * DIP + h * HP + p];
        const float gate = z / (1.f + expf(-z));
        g_y[(size_t)bt * DI + h * HP + p] = (acc + Dh * xv) * gate;
    }
}

// ---------------- RMS norm over D_INNER, in place ----------------
__global__ __launch_bounds__(256)
void rmsnorm_kernel(const float* __restrict__ norm_w)
{
    const int bt = blockIdx.x;
    float* row = g_y + (size_t)bt * DI;
    float v[16];
    float ss = 0.f;
    #pragma unroll
    for (int i = 0; i < 16; i++) {
        v[i] = row[threadIdx.x + i * 256];
        ss = fmaf(v[i], v[i], ss);
    }
    #pragma unroll
    for (int o = 16; o > 0; o >>= 1) ss += __shfl_xor_sync(0xffffffffu, ss, o);
    __shared__ float sred[8];
    const int lane = threadIdx.x & 31, warp = threadIdx.x >> 5;
    if (lane == 0) sred[warp] = ss;
    __syncthreads();
    float tot = 0.f;
    #pragma unroll
    for (int w = 0; w < 8; w++) tot += sred[w];
    const float scale = rsqrtf(tot * (1.f / DI) + 1e-5f);
    #pragma unroll
    for (int i = 0; i < 16; i++)
        row[threadIdx.x + i * 256] = v[i] * scale * norm_w[threadIdx.x + i * 256];
}

// ---------------- classifier head: out[bt,c] = oh[bt,:] . cls_w[c,:] + cls_b[c] ----------------
__global__ __launch_bounds__(256)
void cls_kernel(const float* __restrict__ cls_w, const float* __restrict__ cls_b,
                float* __restrict__ out)
{
    const int bt = blockIdx.x;
    const float* row = g_oh + (size_t)bt * DM;
    float a0 = 0.f, a1 = 0.f, a2 = 0.f, a3 = 0.f;
    for (int k = threadIdx.x; k < DM; k += 256) {
        float xv = row[k];
        a0 = fmaf(xv, __ldg(cls_w + k),          a0);
        a1 = fmaf(xv, __ldg(cls_w + DM + k),     a1);
        a2 = fmaf(xv, __ldg(cls_w + 2 * DM + k), a2);
        a3 = fmaf(xv, __ldg(cls_w + 3 * DM + k), a3);
    }
    #pragma unroll
    for (int o = 16; o > 0; o >>= 1) {
        a0 += __shfl_xor_sync(0xffffffffu, a0, o);
        a1 += __shfl_xor_sync(0xffffffffu, a1, o);
        a2 += __shfl_xor_sync(0xffffffffu, a2, o);
        a3 += __shfl_xor_sync(0xffffffffu, a3, o);
    }
    __shared__ float sred[8][4];
    const int lane = threadIdx.x & 31, warp = threadIdx.x >> 5;
    if (lane == 0) { sred[warp][0] = a0; sred[warp][1] = a1; sred[warp][2] = a2; sred[warp][3] = a3; }
    __syncthreads();
    if (threadIdx.x < 4) {
        float s = cls_b[threadIdx.x];
        #pragma unroll
        for (int w = 0; w < 8; w++) s += sred[w][threadIdx.x];
        out[bt * NCLS + threadIdx.x] = s;
    }
}

// ---------------- launcher ----------------
extern "C" void kernel_launch(void* const* d_in, const int* in_sizes, int n_in,
                              void* d_out, int out_size)
{
    (void)in_sizes; (void)n_in; (void)out_size;
    const float* x          = (const float*)d_in[0];   // (4,2048,2048)
    const float* in_proj_w  = (const float*)d_in[1];   // (8448,2048)
    const float* conv_w     = (const float*)d_in[2];   // (4224,4)
    const float* conv_b     = (const float*)d_in[3];   // (4224,)
    const float* dt_bias    = (const float*)d_in[4];   // (64,)
    const float* A_log      = (const float*)d_in[5];   // (64,)
    const float* Dp         = (const float*)d_in[6];   // (64,)
    const float* norm_w     = (const float*)d_in[7];   // (4096,)
    const float* out_proj_w = (const float*)d_in[8];   // (2048,4096)
    const float* cls_w      = (const float*)d_in[9];   // (4,2048)
    const float* cls_b      = (const float*)d_in[10];  // (4,)
    float* out = (float*)d_out;                        // (4,2048,4)

    float *zx, *y, *oh;
    cudaGetSymbolAddress((void**)&zx, g_zx);
    cudaGetSymbolAddress((void**)&y,  g_y);
    cudaGetSymbolAddress((void**)&oh, g_oh);

    // 1) in_proj: (8192,2048) x (8448,2048)^T -> (8192,8448)
    {
        dim3 grid(DIP / 128, BL / 128);
        gemm_nt_128<<<grid, 256>>>(x, in_proj_w, zx, BL, DIP, DM);
    }
    // 2) conv + silu + dt/dA
    conv_prep_kernel<<<BL, 256>>>(conv_w, conv_b, dt_bias, A_log);
    // 3) selective scan (+ D*x, silu(z) gate)
    scan_kernel<<<B_ * HN, 64>>>(Dp);
    // 4) RMS norm in place
    rmsnorm_kernel<<<BL, 256>>>(norm_w);
    // 5) out_proj: (8192,4096) x (2048,4096)^T -> (8192,2048)
    {
        dim3 grid(DM / 128, BL / 128);
        gemm_nt_128<<<grid, 256>>>(y, out_proj_w, oh, BL, DM, DI);
    }
    // 6) classifier head
    cls_kernel<<<BL, 256>>>(cls_w, cls_b, out);
}

// round 3
// speedup vs baseline: 1.6182x; 1.6182x over previous
#include <cuda_runtime.h>
#include <math.h>
#include <stdint.h>

#define B_    4
#define L_    2048
#define DM    2048
#define DI    4096
#define DST   64
#define HN    64
#define HP    64
#define CONVD 4224
#define DIP   8448
#define BL    (B_*L_)          // 8192
#define NCLS  4

// ---------------- scratch (static device globals; no allocation) ----------------
__device__ float g_zx[BL * DIP];        // in_proj output  (8192 x 8448)
__device__ float g_xh[BL * DI];         // conv+silu x part
__device__ float g_Bm[BL * DST];
__device__ float g_Cm[BL * DST];
__device__ float g_dt[BL * HN];
__device__ float g_dA[BL * HN];
__device__ float g_y [BL * DI];
__device__ float g_oh[BL * DM];

// ---------------- tf32 helpers ----------------
__device__ __forceinline__ unsigned f2tf32(float f) {
    unsigned u;
    asm("cvt.rna.tf32.f32 %0, %1;" : "=r"(u) : "f"(f));
    return u;
}
__device__ __forceinline__ void mma_tf32(float c[4], const unsigned a[4], const unsigned b[2]) {
    asm volatile(
        "mma.sync.aligned.m16n8k8.row.col.f32.tf32.tf32.f32 "
        "{%0,%1,%2,%3}, {%4,%5,%6,%7}, {%8,%9}, {%0,%1,%2,%3};"
        : "+f"(c[0]), "+f"(c[1]), "+f"(c[2]), "+f"(c[3])
        : "r"(a[0]), "r"(a[1]), "r"(a[2]), "r"(a[3]),
          "r"(b[0]), "r"(b[1]));
}

// ---------------- TF32 tensor-core GEMM:  C[M,N] = A[M,K] * W[N,K]^T ----------------
// 128x128 tile, BK=16, 256 threads (8 warps, 2x4), warp tile 64x32 via m16n8k8.
// Smem XOR-swizzled: element (k,row) stored at [k][row ^ 8*((k>>2)&3)], stride 136.
// Conflict-free STS and fragment LDS. Register-prefetch pipeline.
__global__ __launch_bounds__(256, 2)
void gemm_tf32_128(const float* __restrict__ A, const float* __restrict__ W,
                   float* __restrict__ C, int M, int N, int K)
{
    __shared__ unsigned As[16][136];
    __shared__ unsigned Bs[16][136];

    const int tid  = threadIdx.x;
    const int warp = tid >> 5;
    const int lane = tid & 31;
    const int wm = warp & 1;         // 0..1
    const int wn = warp >> 1;        // 0..3
    const int g  = lane >> 2;        // groupID 0..7
    const int t  = lane & 3;         // thread-in-group
    const int bm = blockIdx.y << 7;
    const int bn = blockIdx.x << 7;

    const int lrow = tid >> 2;            // 0..63
    const int kq   = (tid & 3) << 2;      // 0,4,8,12
    const int swzS = (tid & 3) << 3;      // = 8*((k>>2)&3) for k in [kq, kq+3]

    const float* Ap = A + (size_t)(bm + lrow) * K + kq;
    const float* Wp = W + (size_t)(bn + lrow) * K + kq;
    const size_t rstep = (size_t)64 * K;

    float acc[4][4][4];
    #pragma unroll
    for (int i = 0; i < 4; i++)
        #pragma unroll
        for (int j = 0; j < 4; j++)
            #pragma unroll
            for (int c = 0; c < 4; c++) acc[i][j][c] = 0.f;

    float4 av0, av1, wv0, wv1;
    av0 = *(const float4*)Ap;            av1 = *(const float4*)(Ap + rstep);
    wv0 = *(const float4*)Wp;            wv1 = *(const float4*)(Wp + rstep);

    auto sts = [&]() {
        const float* a0 = &av0.x; const float* a1 = &av1.x;
        const float* w0 = &wv0.x; const float* w1 = &wv1.x;
        #pragma unroll
        for (int j = 0; j < 4; j++) {
            const int k = kq + j;
            As[k][lrow ^ swzS]        = f2tf32(a0[j]);
            As[k][(lrow + 64) ^ swzS] = f2tf32(a1[j]);
            Bs[k][lrow ^ swzS]        = f2tf32(w0[j]);
            Bs[k][(lrow + 64) ^ swzS] = f2tf32(w1[j]);
        }
    };
    sts();
    __syncthreads();

    const int KT = K >> 4;
    for (int kt = 0; kt < KT; kt++) {
        if (kt + 1 < KT) {
            const float* Ap2 = Ap + (kt + 1) * 16;
            const float* Wp2 = Wp + (kt + 1) * 16;
            av0 = *(const float4*)Ap2;   av1 = *(const float4*)(Ap2 + rstep);
            wv0 = *(const float4*)Wp2;   wv1 = *(const float4*)(Wp2 + rstep);
        }
        #pragma unroll
        for (int kk = 0; kk < 2; kk++) {
            const int k0 = kk * 8 + t;
            const int k1 = k0 + 4;
            const int s0 = ((2 * kk)     & 3) << 3;   // swizzle for k0 plane
            const int s1 = ((2 * kk + 1) & 3) << 3;   // swizzle for k1 plane
            unsigned a[4][4], b[4][2];
            #pragma unroll
            for (int mt = 0; mt < 4; mt++) {
                const int r = wm * 64 + mt * 16 + g;
                a[mt][0] = As[k0][r       ^ s0];
                a[mt][1] = As[k0][(r + 8) ^ s0];
                a[mt][2] = As[k1][r       ^ s1];
                a[mt][3] = As[k1][(r + 8) ^ s1];
            }
            #pragma unroll
            for (int nt = 0; nt < 4; nt++) {
                const int c = wn * 32 + nt * 8 + g;
                b[nt][0] = Bs[k0][c ^ s0];
                b[nt][1] = Bs[k1][c ^ s1];
            }
            #pragma unroll
            for (int mt = 0; mt < 4; mt++)
                #pragma unroll
                for (int nt = 0; nt < 4; nt++)
                    mma_tf32(acc[mt][nt], a[mt], b[nt]);
        }
        if (kt + 1 < KT) {
            __syncthreads();
            sts();
            __syncthreads();
        }
    }

    #pragma unroll
    for (int mt = 0; mt < 4; mt++) {
        #pragma unroll
        for (int nt = 0; nt < 4; nt++) {
            const int r0 = bm + wm * 64 + mt * 16 + g;
            const int c0 = bn + wn * 32 + nt * 8 + 2 * t;
            float2 v01 = make_float2(acc[mt][nt][0], acc[mt][nt][1]);
            float2 v23 = make_float2(acc[mt][nt][2], acc[mt][nt][3]);
            *(float2*)&C[(size_t)r0 * N + c0]       = v01;
            *(float2*)&C[(size_t)(r0 + 8) * N + c0] = v23;
        }
    }
}

// ---------------- exact fp32 dt path: dt_raw = x . W_dt^T, then softplus/exp ----------------
// C tile: 128 bt x 64 heads per block, K=2048. Writes g_dt/g_dA directly.
__global__ __launch_bounds__(256)
void dt_exact_kernel(const float* __restrict__ x, const float* __restrict__ in_proj_w,
                     const float* __restrict__ dt_bias, const float* __restrict__ A_log)
{
    __shared__ float As[16][132];
    __shared__ float Ws[16][68];
    const int tid = threadIdx.x;
    const int bt0 = blockIdx.x << 7;
    const int tm = tid >> 3;     // 0..31 -> rows tm + i*32
    const int tn = tid & 7;      // 0..7  -> cols tn + j*8
    const float* Wdt = in_proj_w + (size_t)(DI + CONVD) * DM;

    float acc[4][8];
    #pragma unroll
    for (int i = 0; i < 4; i++)
        #pragma unroll
        for (int j = 0; j < 8; j++) acc[i][j] = 0.f;

    for (int k0 = 0; k0 < DM; k0 += 16) {
        #pragma unroll
        for (int i = 0; i < 2; i++) {
            const int lin = tid + (i << 8);
            const int row = lin >> 2;
            const int kk  = (lin & 3) << 2;
            float4 v = *(const float4*)(x + (size_t)(bt0 + row) * DM + k0 + kk);
            As[kk + 0][row] = v.x; As[kk + 1][row] = v.y;
            As[kk + 2][row] = v.z; As[kk + 3][row] = v.w;
        }
        {
            const int row = tid >> 2;          // 0..63
            const int kk  = (tid & 3) << 2;
            float4 w = *(const float4*)(Wdt + (size_t)row * DM + k0 + kk);
            Ws[kk + 0][row] = w.x; Ws[kk + 1][row] = w.y;
            Ws[kk + 2][row] = w.z; Ws[kk + 3][row] = w.w;
        }
        __syncthreads();
        #pragma unroll
        for (int k = 0; k < 16; k++) {
            float a[4], b[8];
            #pragma unroll
            for (int i = 0; i < 4; i++) a[i] = As[k][tm + i * 32];
            #pragma unroll
            for (int j = 0; j < 8; j++) b[j] = Ws[k][tn + j * 8];
            #pragma unroll
            for (int i = 0; i < 4; i++)
                #pragma unroll
                for (int j = 0; j < 8; j++)
                    acc[i][j] = fmaf(a[i], b[j], acc[i][j]);
        }
        __syncthreads();
    }
    #pragma unroll
    for (int i = 0; i < 4; i++) {
        #pragma unroll
        for (int j = 0; j < 8; j++) {
            const int bt = bt0 + tm + i * 32;
            const int h  = tn + j * 8;
            float dtr = acc[i][j] + __ldg(dt_bias + h);
            float dts = (dtr > 20.f) ? dtr : log1pf(expf(dtr));
            g_dt[bt * HN + h] = dts;
            g_dA[bt * HN + h] = expf(-expf(__ldg(A_log + h)) * dts);
        }
    }
}

// ---------------- conv1d(depthwise, width 4) + SiLU ----------------
__global__ void conv_prep_kernel(const float* __restrict__ conv_w,
                                 const float* __restrict__ conv_b)
{
    const int bt = blockIdx.x;
    const int b  = bt / L_;
    const int t  = bt % L_;

    for (int c = threadIdx.x; c < CONVD; c += blockDim.x) {
        float4 wv = *(const float4*)(conv_w + c * 4);
        float s = conv_b[c];
        const float wk[4] = {wv.x, wv.y, wv.z, wv.w};
        #pragma unroll
        for (int k = 0; k < 4; k++) {
            int tt = t - 3 + k;
            float xv = (tt >= 0) ? g_zx[(size_t)(b * L_ + tt) * DIP + DI + c] : 0.f;
            s = fmaf(xv, wk[k], s);
        }
        float sil = s / (1.f + expf(-s));
        if (c < DI)            g_xh[(size_t)bt * DI + c]       = sil;
        else if (c < DI + DST) g_Bm[bt * DST + (c - DI)]        = sil;
        else                   g_Cm[bt * DST + (c - DI - DST)]  = sil;
    }
}

// ---------------- sequential selective scan + D*x + silu(z) gating ----------------
__global__ __launch_bounds__(64)
void scan_kernel(const float* __restrict__ Dp)
{
    const int b = blockIdx.x >> 6;
    const int h = blockIdx.x & 63;
    const int p = threadIdx.x;
    const float Dh = __ldg(Dp + h);

    float hs[DST];
    #pragma unroll
    for (int n = 0; n < DST; n++) hs[n] = 0.f;

    for (int t = 0; t < L_; t++) {
        const int bt = b * L_ + t;
        const float dA = __ldg(&g_dA[bt * HN + h]);
        const float dt = __ldg(&g_dt[bt * HN + h]);
        const float xv = g_xh[(size_t)bt * DI + h * HP + p];
        const float u  = dt * xv;
        const float4* Bv = (const float4*)(g_Bm + bt * DST);
        const float4* Cv = (const float4*)(g_Cm + bt * DST);
        float acc = 0.f;
        #pragma unroll
        for (int j = 0; j < 16; j++) {
            float4 Bq = __ldg(&Bv[j]);
            float4 Cq = __ldg(&Cv[j]);
            hs[4*j+0] = fmaf(hs[4*j+0], dA, u * Bq.x); acc = fmaf(hs[4*j+0], Cq.x, acc);
            hs[4*j+1] = fmaf(hs[4*j+1], dA, u * Bq.y); acc = fmaf(hs[4*j+1], Cq.y, acc);
            hs[4*j+2] = fmaf(hs[4*j+2], dA, u * Bq.z); acc = fmaf(hs[4*j+2], Cq.z, acc);
            hs[4*j+3] = fmaf(hs[4*j+3], dA, u * Bq.w); acc = fmaf(hs[4*j+3], Cq.w, acc);
        }
        const float z = g_zx[(size_t)bt * DIP + h * HP + p];
        const float gate = z / (1.f + expf(-z));
        g_y[(size_t)bt * DI + h * HP + p] = (acc + Dh * xv) * gate;
    }
}

// ---------------- RMS norm over D_INNER, in place ----------------
__global__ __launch_bounds__(256)
void rmsnorm_kernel(const float* __restrict__ norm_w)
{
    const int bt = blockIdx.x;
    float* row = g_y + (size_t)bt * DI;
    float v[16];
    float ss = 0.f;
    #pragma unroll
    for (int i = 0; i < 16; i++) {
        v[i] = row[threadIdx.x + i * 256];
        ss = fmaf(v[i], v[i], ss);
    }
    #pragma unroll
    for (int o = 16; o > 0; o >>= 1) ss += __shfl_xor_sync(0xffffffffu, ss, o);
    __shared__ float sred[8];
    const int lane = threadIdx.x & 31, warp = threadIdx.x >> 5;
    if (lane == 0) sred[warp] = ss;
    __syncthreads();
    float tot = 0.f;
    #pragma unroll
    for (int w = 0; w < 8; w++) tot += sred[w];
    const float scale = rsqrtf(tot * (1.f / DI) + 1e-5f);
    #pragma unroll
    for (int i = 0; i < 16; i++)
        row[threadIdx.x + i * 256] = v[i] * scale * norm_w[threadIdx.x + i * 256];
}

// ---------------- classifier head ----------------
__global__ __launch_bounds__(256)
void cls_kernel(const float* __restrict__ cls_w, const float* __restrict__ cls_b,
                float* __restrict__ out)
{
    const int bt = blockIdx.x;
    const float* row = g_oh + (size_t)bt * DM;
    float a0 = 0.f, a1 = 0.f, a2 = 0.f, a3 = 0.f;
    for (int k = threadIdx.x; k < DM; k += 256) {
        float xv = row[k];
        a0 = fmaf(xv, __ldg(cls_w + k),          a0);
        a1 = fmaf(xv, __ldg(cls_w + DM + k),     a1);
        a2 = fmaf(xv, __ldg(cls_w + 2 * DM + k), a2);
        a3 = fmaf(xv, __ldg(cls_w + 3 * DM + k), a3);
    }
    #pragma unroll
    for (int o = 16; o > 0; o >>= 1) {
        a0 += __shfl_xor_sync(0xffffffffu, a0, o);
        a1 += __shfl_xor_sync(0xffffffffu, a1, o);
        a2 += __shfl_xor_sync(0xffffffffu, a2, o);
        a3 += __shfl_xor_sync(0xffffffffu, a3, o);
    }
    __shared__ float sred[8][4];
    const int lane = threadIdx.x & 31, warp = threadIdx.x >> 5;
    if (lane == 0) { sred[warp][0] = a0; sred[warp][1] = a1; sred[warp][2] = a2; sred[warp][3] = a3; }
    __syncthreads();
    if (threadIdx.x < 4) {
        float s = cls_b[threadIdx.x];
        #pragma unroll
        for (int w = 0; w < 8; w++) s += sred[w][threadIdx.x];
        out[bt * NCLS + threadIdx.x] = s;
    }
}

// ---------------- launcher ----------------
extern "C" void kernel_launch(void* const* d_in, const int* in_sizes, int n_in,
                              void* d_out, int out_size)
{
    (void)in_sizes; (void)n_in; (void)out_size;
    const float* x          = (const float*)d_in[0];
    const float* in_proj_w  = (const float*)d_in[1];
    const float* conv_w     = (const float*)d_in[2];
    const float* conv_b     = (const float*)d_in[3];
    const float* dt_bias    = (const float*)d_in[4];
    const float* A_log      = (const float*)d_in[5];
    const float* Dp         = (const float*)d_in[6];
    const float* norm_w     = (const float*)d_in[7];
    const float* out_proj_w = (const float*)d_in[8];
    const float* cls_w      = (const float*)d_in[9];
    const float* cls_b      = (const float*)d_in[10];
    float* out = (float*)d_out;

    float *zx, *y, *oh;
    cudaGetSymbolAddress((void**)&zx, g_zx);
    cudaGetSymbolAddress((void**)&y,  g_y);
    cudaGetSymbolAddress((void**)&oh, g_oh);

    // 1) in_proj GEMM (tf32 tensor cores): (8192,2048) x (8448,2048)^T
    {
        dim3 grid(DIP / 128, BL / 128);
        gemm_tf32_128<<<grid, 256>>>(x, in_proj_w, zx, BL, DIP, DM);
    }
    // 2) exact fp32 dt path (overrides tf32 dt columns)
    dt_exact_kernel<<<BL / 128, 256>>>(x, in_proj_w, dt_bias, A_log);
    // 3) conv + silu
    conv_prep_kernel<<<BL, 256>>>(conv_w, conv_b);
    // 4) selective scan (+ D*x, silu(z) gate)
    scan_kernel<<<B_ * HN, 64>>>(Dp);
    // 5) RMS norm in place
    rmsnorm_kernel<<<BL, 256>>>(norm_w);
    // 6) out_proj GEMM (tf32): (8192,4096) x (2048,4096)^T
    {
        dim3 grid(DM / 128, BL / 128);
        gemm_tf32_128<<<grid, 256>>>(y, out_proj_w, oh, BL, DM, DI);
    }
    // 7) classifier head
    cls_kernel<<<BL, 256>>>(cls_w, cls_b, out);
}

// round 5
// speedup vs baseline: 1.7056x; 1.0540x over previous
#include <cuda_runtime.h>
#include <math.h>
#include <stdint.h>

#define B_    4
#define L_    2048
#define DM    2048
#define DI    4096
#define DST   64
#define HN    64
#define HP    64
#define CONVD 4224
#define DIP   8448
#define BL    (B_*L_)          // 8192
#define NCLS  4

// ---------------- scratch (static device globals; no allocation) ----------------
__device__ float g_zx[BL * DIP];
__device__ float g_xh[BL * DI];
__device__ float g_Bm[BL * DST];
__device__ float g_Cm[BL * DST];
__device__ float g_dt[BL * HN];
__device__ float g_dA[BL * HN];
__device__ float g_y [BL * DI];
__device__ float g_oh[BL * DM];

// ---------------- helpers ----------------
__device__ __forceinline__ unsigned f2tf32(float f) {
    unsigned u;
    asm("cvt.rna.tf32.f32 %0, %1;" : "=r"(u) : "f"(f));
    return u;
}
__device__ __forceinline__ uint32_t smem_u32(const void* p) {
    uint32_t a;
    asm("{ .reg .u64 t; cvta.to.shared.u64 t, %1; cvt.u32.u64 %0, t; }" : "=r"(a) : "l"(p));
    return a;
}
__device__ __forceinline__ void cp16(uint32_t saddr, const void* gptr) {
    asm volatile("cp.async.ca.shared.global [%0], [%1], 16;" :: "r"(saddr), "l"(gptr) : "memory");
}
__device__ __forceinline__ void cp_commit() {
    asm volatile("cp.async.commit_group;" ::: "memory");
}
__device__ __forceinline__ void cp_wait2() {
    asm volatile("cp.async.wait_group 2;" ::: "memory");
}
__device__ __forceinline__ void mma_tf32(float c[4], const unsigned a[4], const unsigned b[2]) {
    asm volatile(
        "mma.sync.aligned.m16n8k8.row.col.f32.tf32.tf32.f32 "
        "{%0,%1,%2,%3}, {%4,%5,%6,%7}, {%8,%9}, {%0,%1,%2,%3};"
        : "+f"(c[0]), "+f"(c[1]), "+f"(c[2]), "+f"(c[3])
        : "r"(a[0]), "r"(a[1]), "r"(a[2]), "r"(a[3]),
          "r"(b[0]), "r"(b[1]));
}

// smem: 4 stages x (A[128][20] + B[128][20]) fp32; row stride 20 floats = 80 B
#define ROWSTR   20
#define STAGE_A_BYTES (128 * 80)            // 10240
#define STAGE_BYTES   (2 * STAGE_A_BYTES)   // 20480
#define NSTAGE   4
#define SMEM_BYTES (NSTAGE * STAGE_BYTES)   // 81920

// ---------------- TF32 mma.sync GEMM, cp.async 4-stage:  C[M,N] = A[M,K] * W[N,K]^T ----------------
// 128x128 tile, BK=16, 256 threads (8 warps 2x4), warp tile 64x32 via m16n8k8.
__global__ __launch_bounds__(256, 2)
void gemm_tf32_ca(const float* __restrict__ A, const float* __restrict__ W,
                  float* __restrict__ C, int M, int N, int K)
{
    extern __shared__ __align__(16) char smem[];
    const uint32_t sb = smem_u32(smem);
    const float* Sf = (const float*)smem;

    const int tid  = threadIdx.x;
    const int warp = tid >> 5;
    const int lane = tid & 31;
    const int wm = warp & 1;
    const int wn = warp >> 1;
    const int g  = lane >> 2;
    const int t  = lane & 3;
    const int bm = blockIdx.y << 7;
    const int bn = blockIdx.x << 7;

    // producer mapping: thread handles rows r0, r0+64 at 16B chunk k4, for A and B
    const int r0 = tid >> 2;          // 0..63
    const int k4 = tid & 3;           // 16B chunk within BK=16 row

    const float* Ag0 = A + (size_t)(bm + r0) * K + k4 * 4;
    const float* Wg0 = W + (size_t)(bn + r0) * K + k4 * 4;
    const size_t rows64 = (size_t)64 * K;
    const uint32_t sA0 = sb + (uint32_t)(r0 * 80 + k4 * 16);

    float acc[4][4][4];
    #pragma unroll
    for (int i = 0; i < 4; i++)
        #pragma unroll
        for (int j = 0; j < 4; j++)
            #pragma unroll
            for (int c = 0; c < 4; c++) acc[i][j][c] = 0.f;

    const int KT = K >> 4;

    auto issue_stage = [&](int kt, int s) {
        const float* Ag = Ag0 + kt * 16;
        const float* Wg = Wg0 + kt * 16;
        const uint32_t sA = sA0 + s * STAGE_BYTES;
        const uint32_t sB = sA + STAGE_A_BYTES;
        cp16(sA,            Ag);
        cp16(sA + 64 * 80,  Ag + rows64);
        cp16(sB,            Wg);
        cp16(sB + 64 * 80,  Wg + rows64);
    };

    issue_stage(0, 0); cp_commit();
    issue_stage(1, 1); cp_commit();
    issue_stage(2, 2); cp_commit();
    cp_wait2();
    __syncthreads();

    for (int kt = 0; kt < KT; kt++) {
        const int s = kt & 3;
        const float* Af = Sf + s * (STAGE_BYTES / 4);
        const float* Bf = Af + (STAGE_A_BYTES / 4);

        #pragma unroll
        for (int kk = 0; kk < 2; kk++) {
            const int k0 = kk * 8 + t;
            unsigned a[4][4], b[4][2];
            #pragma unroll
            for (int mt = 0; mt < 4; mt++) {
                const int r = wm * 64 + mt * 16 + g;
                a[mt][0] = f2tf32(Af[r * ROWSTR + k0]);
                a[mt][1] = f2tf32(Af[(r + 8) * ROWSTR + k0]);
                a[mt][2] = f2tf32(Af[r * ROWSTR + k0 + 4]);
                a[mt][3] = f2tf32(Af[(r + 8) * ROWSTR + k0 + 4]);
            }
            #pragma unroll
            for (int nt = 0; nt < 4; nt++) {
                const int c = wn * 32 + nt * 8 + g;
                b[nt][0] = f2tf32(Bf[c * ROWSTR + k0]);
                b[nt][1] = f2tf32(Bf[c * ROWSTR + k0 + 4]);
            }
            #pragma unroll
            for (int mt = 0; mt < 4; mt++)
                #pragma unroll
                for (int nt = 0; nt < 4; nt++)
                    mma_tf32(acc[mt][nt], a[mt], b[nt]);
        }

        if (kt + 3 < KT) issue_stage(kt + 3, (kt + 3) & 3);
        cp_commit();
        if (kt + 1 < KT) {
            cp_wait2();
            __syncthreads();
        }
    }

    #pragma unroll
    for (int mt = 0; mt < 4; mt++) {
        #pragma unroll
        for (int nt = 0; nt < 4; nt++) {
            const int rr = bm + wm * 64 + mt * 16 + g;
            const int c0 = bn + wn * 32 + nt * 8 + 2 * t;
            *(float2*)&C[(size_t)rr * N + c0]       = make_float2(acc[mt][nt][0], acc[mt][nt][1]);
            *(float2*)&C[(size_t)(rr + 8) * N + c0] = make_float2(acc[mt][nt][2], acc[mt][nt][3]);
        }
    }
}

// ---------------- exact fp32 dt path: dt_raw = x . W_dt^T, then softplus/exp ----------------
__global__ __launch_bounds__(256)
void dt_exact_kernel(const float* __restrict__ x, const float* __restrict__ in_proj_w,
                     const float* __restrict__ dt_bias, const float* __restrict__ A_log)
{
    __shared__ float As[16][132];
    __shared__ float Ws[16][68];
    const int tid = threadIdx.x;
    const int bt0 = blockIdx.x << 7;
    const int tm = tid >> 3;
    const int tn = tid & 7;
    const float* Wdt = in_proj_w + (size_t)(DI + CONVD) * DM;

    float acc[4][8];
    #pragma unroll
    for (int i = 0; i < 4; i++)
        #pragma unroll
        for (int j = 0; j < 8; j++) acc[i][j] = 0.f;

    for (int k0 = 0; k0 < DM; k0 += 16) {
        #pragma unroll
        for (int i = 0; i < 2; i++) {
            const int lin = tid + (i << 8);
            const int r = lin >> 2;
            const int kk = (lin & 3) << 2;
            float4 v = *(const float4*)(x + (size_t)(bt0 + r) * DM + k0 + kk);
            As[kk + 0][r] = v.x; As[kk + 1][r] = v.y;
            As[kk + 2][r] = v.z; As[kk + 3][r] = v.w;
        }
        {
            const int r = tid >> 2;
            const int kk = (tid & 3) << 2;
            float4 w = *(const float4*)(Wdt + (size_t)r * DM + k0 + kk);
            Ws[kk + 0][r] = w.x; Ws[kk + 1][r] = w.y;
            Ws[kk + 2][r] = w.z; Ws[kk + 3][r] = w.w;
        }
        __syncthreads();
        #pragma unroll
        for (int k = 0; k < 16; k++) {
            float a[4], b[8];
            #pragma unroll
            for (int i = 0; i < 4; i++) a[i] = As[k][tm + i * 32];
            #pragma unroll
            for (int j = 0; j < 8; j++) b[j] = Ws[k][tn + j * 8];
            #pragma unroll
            for (int i = 0; i < 4; i++)
                #pragma unroll
                for (int j = 0; j < 8; j++)
                    acc[i][j] = fmaf(a[i], b[j], acc[i][j]);
        }
        __syncthreads();
    }
    #pragma unroll
    for (int i = 0; i < 4; i++) {
        #pragma unroll
        for (int j = 0; j < 8; j++) {
            const int bt = bt0 + tm + i * 32;
            const int h  = tn + j * 8;
            float dtr = acc[i][j] + __ldg(dt_bias + h);
            float dts = (dtr > 20.f) ? dtr : log1pf(expf(dtr));
            g_dt[bt * HN + h] = dts;
            g_dA[bt * HN + h] = expf(-expf(__ldg(A_log + h)) * dts);
        }
    }
}

// ---------------- conv1d(depthwise, width 4) + SiLU ----------------
__global__ void conv_prep_kernel(const float* __restrict__ conv_w,
                                 const float* __restrict__ conv_b)
{
    const int bt = blockIdx.x;
    const int b  = bt / L_;
    const int t  = bt % L_;

    for (int c = threadIdx.x; c < CONVD; c += blockDim.x) {
        float4 wv = *(const float4*)(conv_w + c * 4);
        float s = conv_b[c];
        const float wk[4] = {wv.x, wv.y, wv.z, wv.w};
        #pragma unroll
        for (int k = 0; k < 4; k++) {
            int tt = t - 3 + k;
            float xv = (tt >= 0) ? g_zx[(size_t)(b * L_ + tt) * DIP + DI + c] : 0.f;
            s = fmaf(xv, wk[k], s);
        }
        float sil = s / (1.f + expf(-s));
        if (c < DI)            g_xh[(size_t)bt * DI + c]       = sil;
        else if (c < DI + DST) g_Bm[bt * DST + (c - DI)]        = sil;
        else                   g_Cm[bt * DST + (c - DI - DST)]  = sil;
    }
}

// ---------------- sequential selective scan + D*x + silu(z) gating ----------------
__global__ __launch_bounds__(64)
void scan_kernel(const float* __restrict__ Dp)
{
    const int b = blockIdx.x >> 6;
    const int h = blockIdx.x & 63;
    const int p = threadIdx.x;
    const float Dh = __ldg(Dp + h);

    float hs[DST];
    #pragma unroll
    for (int n = 0; n < DST; n++) hs[n] = 0.f;

    for (int t = 0; t < L_; t++) {
        const int bt = b * L_ + t;
        const float dA = __ldg(&g_dA[bt * HN + h]);
        const float dt = __ldg(&g_dt[bt * HN + h]);
        const float xv = g_xh[(size_t)bt * DI + h * HP + p];
        const float u  = dt * xv;
        const float4* Bv = (const float4*)(g_Bm + bt * DST);
        const float4* Cv = (const float4*)(g_Cm + bt * DST);
        float acc = 0.f;
        #pragma unroll
        for (int j = 0; j < 16; j++) {
            float4 Bq = __ldg(&Bv[j]);
            float4 Cq = __ldg(&Cv[j]);
            hs[4*j+0] = fmaf(hs[4*j+0], dA, u * Bq.x); acc = fmaf(hs[4*j+0], Cq.x, acc);
            hs[4*j+1] = fmaf(hs[4*j+1], dA, u * Bq.y); acc = fmaf(hs[4*j+1], Cq.y, acc);
            hs[4*j+2] = fmaf(hs[4*j+2], dA, u * Bq.z); acc = fmaf(hs[4*j+2], Cq.z, acc);
            hs[4*j+3] = fmaf(hs[4*j+3], dA, u * Bq.w); acc = fmaf(hs[4*j+3], Cq.w, acc);
        }
        const float z = g_zx[(size_t)bt * DIP + h * HP + p];
        const float gate = z / (1.f + expf(-z));
        g_y[(size_t)bt * DI + h * HP + p] = (acc + Dh * xv) * gate;
    }
}

// ---------------- RMS norm over D_INNER, in place ----------------
__global__ __launch_bounds__(256)
void rmsnorm_kernel(const float* __restrict__ norm_w)
{
    const int bt = blockIdx.x;
    float* row = g_y + (size_t)bt * DI;
    float v[16];
    float ss = 0.f;
    #pragma unroll
    for (int i = 0; i < 16; i++) {
        v[i] = row[threadIdx.x + i * 256];
        ss = fmaf(v[i], v[i], ss);
    }
    #pragma unroll
    for (int o = 16; o > 0; o >>= 1) ss += __shfl_xor_sync(0xffffffffu, ss, o);
    __shared__ float sred[8];
    const int lane = threadIdx.x & 31, warp = threadIdx.x >> 5;
    if (lane == 0) sred[warp] = ss;
    __syncthreads();
    float tot = 0.f;
    #pragma unroll
    for (int w = 0; w < 8; w++) tot += sred[w];
    const float scale = rsqrtf(tot * (1.f / DI) + 1e-5f);
    #pragma unroll
    for (int i = 0; i < 16; i++)
        row[threadIdx.x + i * 256] = v[i] * scale * norm_w[threadIdx.x + i * 256];
}

// ---------------- classifier head ----------------
__global__ __launch_bounds__(256)
void cls_kernel(const float* __restrict__ cls_w, const float* __restrict__ cls_b,
                float* __restrict__ out)
{
    const int bt = blockIdx.x;
    const float* row = g_oh + (size_t)bt * DM;
    float a0 = 0.f, a1 = 0.f, a2 = 0.f, a3 = 0.f;
    for (int k = threadIdx.x; k < DM; k += 256) {
        float xv = row[k];
        a0 = fmaf(xv, __ldg(cls_w + k),          a0);
        a1 = fmaf(xv, __ldg(cls_w + DM + k),     a1);
        a2 = fmaf(xv, __ldg(cls_w + 2 * DM + k), a2);
        a3 = fmaf(xv, __ldg(cls_w + 3 * DM + k), a3);
    }
    #pragma unroll
    for (int o = 16; o > 0; o >>= 1) {
        a0 += __shfl_xor_sync(0xffffffffu, a0, o);
        a1 += __shfl_xor_sync(0xffffffffu, a1, o);
        a2 += __shfl_xor_sync(0xffffffffu, a2, o);
        a3 += __shfl_xor_sync(0xffffffffu, a3, o);
    }
    __shared__ float sred[8][4];
    const int lane = threadIdx.x & 31, warp = threadIdx.x >> 5;
    if (lane == 0) { sred[warp][0] = a0; sred[warp][1] = a1; sred[warp][2] = a2; sred[warp][3] = a3; }
    __syncthreads();
    if (threadIdx.x < 4) {
        float s = cls_b[threadIdx.x];
        #pragma unroll
        for (int w = 0; w < 8; w++) s += sred[w][threadIdx.x];
        out[bt * NCLS + threadIdx.x] = s;
    }
}

// ---------------- launcher ----------------
extern "C" void kernel_launch(void* const* d_in, const int* in_sizes, int n_in,
                              void* d_out, int out_size)
{
    (void)in_sizes; (void)n_in; (void)out_size;
    const float* x          = (const float*)d_in[0];
    const float* in_proj_w  = (const float*)d_in[1];
    const float* conv_w     = (const float*)d_in[2];
    const float* conv_b     = (const float*)d_in[3];
    const float* dt_bias    = (const float*)d_in[4];
    const float* A_log      = (const float*)d_in[5];
    const float* Dp         = (const float*)d_in[6];
    const float* norm_w     = (const float*)d_in[7];
    const float* out_proj_w = (const float*)d_in[8];
    const float* cls_w      = (const float*)d_in[9];
    const float* cls_b      = (const float*)d_in[10];
    float* out = (float*)d_out;

    float *zx, *y, *oh;
    cudaGetSymbolAddress((void**)&zx, g_zx);
    cudaGetSymbolAddress((void**)&y,  g_y);
    cudaGetSymbolAddress((void**)&oh, g_oh);

    cudaFuncSetAttribute(gemm_tf32_ca, cudaFuncAttributeMaxDynamicSharedMemorySize, SMEM_BYTES);

    // 1) in_proj GEMM (tf32 mma.sync + cp.async): (8192,2048) x (8448,2048)^T
    {
        dim3 grid(DIP / 128, BL / 128);
        gemm_tf32_ca<<<grid, 256, SMEM_BYTES>>>(x, in_proj_w, zx, BL, DIP, DM);
    }
    // 2) exact fp32 dt path
    dt_exact_kernel<<<BL / 128, 256>>>(x, in_proj_w, dt_bias, A_log);
    // 3) conv + silu
    conv_prep_kernel<<<BL, 256>>>(conv_w, conv_b);
    // 4) selective scan (+ D*x, silu(z) gate)
    scan_kernel<<<B_ * HN, 64>>>(Dp);
    // 5) RMS norm in place
    rmsnorm_kernel<<<BL, 256>>>(norm_w);
    // 6) out_proj GEMM: (8192,4096) x (2048,4096)^T
    {
        dim3 grid(DM / 128, BL / 128);
        gemm_tf32_ca<<<grid, 256, SMEM_BYTES>>>(y, out_proj_w, oh, BL, DM, DI);
    }
    // 7) classifier head
    cls_kernel<<<BL, 256>>>(cls_w, cls_b, out);
}